// round 9
// baseline (speedup 1.0000x reference)
#include <cuda_runtime.h>
#include <float.h>

// ChessMoveSelector — algebraically collapsed.
// probs[b,n] = mask * softmax_n( moves[b,n,0]*w0 + moves[b,n,1]*w1 )
// where w = move_w^T @ comb_w[0, BD:].  All batch-constant terms (entire
// conv/fc board branch, biases) cancel inside the row softmax.
//
// Round 9: 2 rows per warp (MLP=2 on the moves DRAM load, w computed once
// per warp instead of once per row), 128 CTAs x 512 thr (1 CTA/SM single
// wave), integer redux.sync reductions, paired int2 lengths load, streaming
// cache hints.

#define NMAX 64
#define MD 128
#define BD 256

// Order-preserving float <-> int monotone mapping for integer max reduction.
__device__ __forceinline__ int f32_to_ordered_s32(float f) {
    int i = __float_as_int(f);
    return (i < 0) ? (i ^ 0x7fffffff) : i;   // now s32 compare == fp32 compare
}

__device__ __forceinline__ float warp_max_f32(float v) {
    int key = f32_to_ordered_s32(v);
    int r;
    asm volatile("redux.sync.max.s32 %0, %1, 0xffffffff;" : "=r"(r) : "r"(key));
    r = (r < 0) ? (r ^ 0x7fffffff) : r;      // invert mapping
    return __int_as_float(r);
}

__device__ __forceinline__ int warp_sum_s32(int v) {
    int r;
    asm volatile("redux.sync.add.s32 %0, %1, 0xffffffff;" : "=r"(r) : "r"(v));
    return r;
}

__global__ void __launch_bounds__(512)
chess_move_softmax_kernel(
    const float4* __restrict__ moves4,   // [B*32] float4 == [B,64,2] floats
    const int2*   __restrict__ lengths2, // [B/2] int2 == lengths[B]
    const float2* __restrict__ move_w2,  // [128] float2 == move_w[128,2]
    const float*  __restrict__ comb_w,   // [384]
    float2*       __restrict__ out2,     // [B*32] float2 == probs[B,64]
    int B)
{
    const int gwarp = (blockIdx.x * blockDim.x + threadIdx.x) >> 5;
    const int lane  = threadIdx.x & 31;
    const int r0    = 2 * gwarp;          // this warp handles rows r0, r0+1
    if (r0 >= B) return;

    // ---- Issue ALL global loads up front: 2 independent moves rows (MLP=2)
    const int2   len2 = lengths2[gwarp];
    const float4 mvA  = __ldcs(&moves4[(size_t)r0 * 32 + lane]);
    const float4 mvB  = __ldcs(&moves4[(size_t)(r0 + 1) * 32 + lane]);

    float cw[4];
    float2 mw[4];
    #pragma unroll
    for (int i = 0; i < 4; i++) {
        const int m = lane + i * 32;
        cw[i] = comb_w[BD + m];
        mw[i] = move_w2[m];
    }

    // ---- Collapsed weight vector w = move_w^T @ comb_w[BD:], once per warp
    // (hidden under the in-flight moves DRAM loads)
    float s0 = 0.f, s1 = 0.f;
    #pragma unroll
    for (int i = 0; i < 4; i++) {
        s0 = fmaf(cw[i], mw[i].x, s0);
        s1 = fmaf(cw[i], mw[i].y, s1);
    }
    #pragma unroll
    for (int off = 16; off > 0; off >>= 1) {
        s0 += __shfl_xor_sync(0xffffffffu, s0, off);
        s1 += __shfl_xor_sync(0xffffffffu, s1, off);
    }
    const float w0 = s0;
    const float w1 = s1;

    // ---- Scores: 2 moves per lane per row ----
    const int  n0  = 2 * lane;
    const bool a0  = (n0     < len2.x);
    const bool a1  = (n0 + 1 < len2.x);
    const bool b0  = (n0     < len2.y);
    const bool b1  = (n0 + 1 < len2.y);

    const float scA0 = fmaf(mvA.x, w0, mvA.y * w1);
    const float scA1 = fmaf(mvA.z, w0, mvA.w * w1);
    const float scB0 = fmaf(mvB.x, w0, mvB.y * w1);
    const float scB1 = fmaf(mvB.z, w0, mvB.w * w1);

    // ---- Per-row masked max (two independent redux ops, overlapped) ----
    const float mxA = warp_max_f32(fmaxf(a0 ? scA0 : -FLT_MAX,
                                         a1 ? scA1 : -FLT_MAX));
    const float mxB = warp_max_f32(fmaxf(b0 ? scB0 : -FLT_MAX,
                                         b1 ? scB1 : -FLT_MAX));

    const float eA0 = a0 ? __expf(scA0 - mxA) : 0.f;   // all in (0, 1]
    const float eA1 = a1 ? __expf(scA1 - mxA) : 0.f;
    const float eB0 = b0 ? __expf(scB0 - mxB) : 0.f;
    const float eB1 = b1 ? __expf(scB1 - mxB) : 0.f;

    // Fixed-point warp sums: e in [0,1], scale 2^24, sum <= 64*2^24 = 2^30.
    const int qA = __float2int_rn(eA0 * 16777216.0f)
                 + __float2int_rn(eA1 * 16777216.0f);
    const int qB = __float2int_rn(eB0 * 16777216.0f)
                 + __float2int_rn(eB1 * 16777216.0f);
    const float sumA = (float)warp_sum_s32(qA);
    const float sumB = (float)warp_sum_s32(qB);
    const float invA = __fdividef(16777216.0f, sumA);
    const float invB = __fdividef(16777216.0f, sumB);

    float2 rA, rB;
    rA.x = eA0 * invA;  rA.y = eA1 * invA;
    rB.x = eB0 * invB;  rB.y = eB1 * invB;
    __stcs(&out2[(size_t)r0 * 32 + lane], rA);
    __stcs(&out2[(size_t)(r0 + 1) * 32 + lane], rB);
}

extern "C" void kernel_launch(void* const* d_in, const int* in_sizes, int n_in,
                              void* d_out, int out_size)
{
    const float4* moves   = (const float4*)d_in[2];
    const int2*   lengths = (const int2*)d_in[3];
    const float2* move_w  = (const float2*)d_in[12];
    const float*  comb_w  = (const float*)d_in[14];
    float2* out = (float2*)d_out;

    const int B = in_sizes[3];                 // 4096 rows
    const int threads = 512;                   // 16 warps -> 32 rows per block
    const int rows_per_block = (threads / 32) * 2;
    const int blocks = (B + rows_per_block - 1) / rows_per_block;  // 128

    chess_move_softmax_kernel<<<blocks, threads>>>(moves, lengths, move_w, comb_w, out, B);
}